// round 2
// baseline (speedup 1.0000x reference)
#include <cuda_runtime.h>
#include <cuda_fp16.h>
#include <cstdint>
#include <cstddef>

// ============================================================================
// SparseLinear: y[8192,4096] = x[8192,4096] @ W[4096,4096] + bias[4096]
//
// Harness emits PTX at compute_103 (no 'a') -> tcgen05 unavailable. Use the
// legacy mma.sync fp16 tensor path (sm_80 ISA, valid everywhere):
//   K1: x fp32 -> fp16  (g_XH,  [M,K])
//   K2: W[K,N] fp32 -> transpose+fp16 (g_WTH, [N,K])  => both operands K-major
//   K3: mma.sync.m16n8k16 GEMM, BM=BN=128 BK=64, 4-stage cp.async pipeline,
//       XOR-swizzled SMEM + ldmatrix, fused bias epilogue (fp32 out).
// fp16 mantissa == tf32 mantissa (11 bits) at 2x the legacy-path rate;
// accumulation is fp32 -> expected norm rel_err ~4e-4.
// ============================================================================

#define D_DIM 4096
#define M_DIM 8192
#define BM 128
#define BN 128
#define BK 64
#define STAGES 4
#define KTILES (D_DIM / BK)            // 64
#define THREADS 256
#define TILE_BYTES (BM * BK * 2)       // 16384 (A or B per stage)
#define STAGE_BYTES (2 * TILE_BYTES)   // 32768
#define SMEM_SIZE (STAGES * STAGE_BYTES)  // 131072

__device__ __align__(256) __half g_XH[(size_t)M_DIM * D_DIM];
__device__ __align__(256) __half g_WTH[(size_t)D_DIM * D_DIM];

// ---------------------------------------------------------------------------
// helpers
// ---------------------------------------------------------------------------
__device__ __forceinline__ uint32_t smem_u32(const void* p) {
    uint32_t a;
    asm("{ .reg .u64 t; cvta.to.shared.u64 t, %1; cvt.u32.u64 %0, t; }"
        : "=r"(a) : "l"(p));
    return a;
}

__device__ __forceinline__ void cp_async16(uint32_t dst, const void* src) {
    asm volatile("cp.async.cg.shared.global [%0], [%1], 16;"
                 :: "r"(dst), "l"(src));
}
__device__ __forceinline__ void cp_commit() {
    asm volatile("cp.async.commit_group;" ::: "memory");
}

__device__ __forceinline__ void ldsm_x4(uint32_t* r, uint32_t addr) {
    asm volatile("ldmatrix.sync.aligned.m8n8.x4.shared.b16 {%0,%1,%2,%3}, [%4];"
                 : "=r"(r[0]), "=r"(r[1]), "=r"(r[2]), "=r"(r[3])
                 : "r"(addr));
}

__device__ __forceinline__ void mma16816(float* c, const uint32_t* a,
                                         uint32_t b0, uint32_t b1) {
    asm volatile(
        "mma.sync.aligned.m16n8k16.row.col.f32.f16.f16.f32 "
        "{%0,%1,%2,%3}, {%4,%5,%6,%7}, {%8,%9}, {%0,%1,%2,%3};"
        : "+f"(c[0]), "+f"(c[1]), "+f"(c[2]), "+f"(c[3])
        : "r"(a[0]), "r"(a[1]), "r"(a[2]), "r"(a[3]), "r"(b0), "r"(b1));
}

// ---------------------------------------------------------------------------
// K1: x fp32 -> fp16
// ---------------------------------------------------------------------------
__global__ void convert_x_kernel(const float4* __restrict__ x) {
    size_t i = (size_t)blockIdx.x * blockDim.x + threadIdx.x;
    float4 v = x[i];
    __half2 h0 = __floats2half2_rn(v.x, v.y);
    __half2 h1 = __floats2half2_rn(v.z, v.w);
    uint2 o;
    o.x = *reinterpret_cast<uint32_t*>(&h0);
    o.y = *reinterpret_cast<uint32_t*>(&h1);
    reinterpret_cast<uint2*>(g_XH)[i] = o;
}

// ---------------------------------------------------------------------------
// K2: W[K,N] fp32 -> WT[N,K] fp16 (32x32 smem transpose tiles)
// ---------------------------------------------------------------------------
__global__ void transpose_w_kernel(const float* __restrict__ W) {
    __shared__ float t[32][33];
    int bx = blockIdx.x * 32, by = blockIdx.y * 32;  // bx: n, by: k
    int tx = threadIdx.x, ty = threadIdx.y;
#pragma unroll
    for (int i = 0; i < 32; i += 8)
        t[ty + i][tx] = W[(size_t)(by + ty + i) * D_DIM + bx + tx];
    __syncthreads();
#pragma unroll
    for (int i = 0; i < 32; i += 8)
        g_WTH[(size_t)(bx + ty + i) * D_DIM + by + tx] =
            __float2half_rn(t[tx][ty + i]);
}

// ---------------------------------------------------------------------------
// K3: GEMM. grid (N/BN, M/BM) = (32, 64), 256 threads (8 warps, 4m x 2n).
// SMEM stage: [A 128x64 half | B 128x64 half], rows 128B, granule-XOR swizzle.
// ---------------------------------------------------------------------------
__global__ __launch_bounds__(THREADS, 1)
void gemm_f16_kernel(const float* __restrict__ bias, float* __restrict__ out) {
    extern __shared__ char smem[];
    const uint32_t sbase = smem_u32(smem);
    const int tid = threadIdx.x;
    const int wid = tid >> 5;
    const int l = tid & 31;
    const int bm = blockIdx.y * BM;
    const int bn = blockIdx.x * BN;
    const int wm = (wid >> 1) * 32;   // warp m offset within tile
    const int wn = (wid & 1) * 64;    // warp n offset within tile

    // --- per-thread cp.async granule map: 2048 granules/stage, 8 per thread
    const __half* gsrc[8];
    uint32_t sdst[8];
#pragma unroll
    for (int j = 0; j < 8; j++) {
        int gi = tid + j * 256;
        int isB = gi >> 10;
        int idx = gi & 1023;
        int r = idx >> 3;   // tile row (A: m, B: n)
        int g = idx & 7;    // 16B granule along k (8 halves)
        gsrc[j] = (isB ? g_WTH + (size_t)(bn + r) * D_DIM
                       : g_XH + (size_t)(bm + r) * D_DIM) + g * 8;
        sdst[j] = (uint32_t)(isB ? TILE_BYTES : 0) + (uint32_t)(r * 128) +
                  (uint32_t)((g ^ (r & 7)) << 4);
    }

    auto load_tile = [&](int kt, int slot) {
        uint32_t sb = sbase + (uint32_t)slot * STAGE_BYTES;
#pragma unroll
        for (int j = 0; j < 8; j++)
            cp_async16(sb + sdst[j], gsrc[j] + kt * BK);
    };

#pragma unroll
    for (int s = 0; s < STAGES - 1; s++) { load_tile(s, s); cp_commit(); }

    float acc[2][8][4] = {};

    // ldmatrix lane addressing (within tile)
    const int arow = wm + (l & 15);        // A: lanes 0-15 rows, 16-31 k+8
    const int akg0 = (l >> 4);
    const int brow_off = (l & 7) + ((l >> 4) << 3);  // B: mats 0/1 low 8 n, 2/3 high
    const int bkg0 = (l >> 3) & 1;

    for (int kt = 0; kt < KTILES; kt++) {
        asm volatile("cp.async.wait_group %0;" :: "n"(STAGES - 2) : "memory");
        __syncthreads();
        const int pf = kt + STAGES - 1;
        if (pf < KTILES) load_tile(pf, pf & (STAGES - 1));
        cp_commit();

        const uint32_t stg = sbase + (uint32_t)(kt & (STAGES - 1)) * STAGE_BYTES;
#pragma unroll
        for (int ks = 0; ks < 4; ks++) {
            uint32_t a[2][4];
#pragma unroll
            for (int mt = 0; mt < 2; mt++) {
                int row = arow + mt * 16;
                uint32_t addr = stg + (uint32_t)(row * 128) +
                                (uint32_t)(((2 * ks + akg0) ^ (row & 7)) << 4);
                ldsm_x4(a[mt], addr);
            }
            uint32_t b[4][4];
#pragma unroll
            for (int p = 0; p < 4; p++) {
                int row = wn + p * 16 + brow_off;
                uint32_t addr = stg + TILE_BYTES + (uint32_t)(row * 128) +
                                (uint32_t)(((2 * ks + bkg0) ^ (row & 7)) << 4);
                ldsm_x4(b[p], addr);
            }
#pragma unroll
            for (int mt = 0; mt < 2; mt++)
#pragma unroll
                for (int p = 0; p < 4; p++) {
                    mma16816(acc[mt][2 * p],     a[mt], b[p][0], b[p][1]);
                    mma16816(acc[mt][2 * p + 1], a[mt], b[p][2], b[p][3]);
                }
        }
    }

    // --- epilogue: y = acc + bias
    const int grp = l >> 2, tig = l & 3;
#pragma unroll
    for (int mt = 0; mt < 2; mt++) {
        const size_t row0 = (size_t)(bm + wm + mt * 16 + grp);
#pragma unroll
        for (int nt = 0; nt < 8; nt++) {
            const int col = bn + wn + nt * 8 + tig * 2;
            const float2 bv = *reinterpret_cast<const float2*>(bias + col);
            float2 v0, v1;
            v0.x = acc[mt][nt][0] + bv.x;
            v0.y = acc[mt][nt][1] + bv.y;
            v1.x = acc[mt][nt][2] + bv.x;
            v1.y = acc[mt][nt][3] + bv.y;
            *reinterpret_cast<float2*>(out + row0 * D_DIM + col) = v0;
            *reinterpret_cast<float2*>(out + (row0 + 8) * D_DIM + col) = v1;
        }
    }
}

// ---------------------------------------------------------------------------
// Launch
// ---------------------------------------------------------------------------
extern "C" void kernel_launch(void* const* d_in, const int* in_sizes, int n_in,
                              void* d_out, int out_size) {
    const float* x    = (const float*)d_in[0];
    const float* W    = (const float*)d_in[1];
    const float* bias = (const float*)d_in[2];
    float* out = (float*)d_out;

    cudaFuncSetAttribute(gemm_f16_kernel,
                         cudaFuncAttributeMaxDynamicSharedMemorySize, SMEM_SIZE);

    convert_x_kernel<<<(int)((size_t)M_DIM * D_DIM / 4 / 256), 256>>>(
        (const float4*)x);
    transpose_w_kernel<<<dim3(D_DIM / 32, D_DIM / 32), dim3(32, 8)>>>(W);
    gemm_f16_kernel<<<dim3(D_DIM / BN, M_DIM / BM), THREADS, SMEM_SIZE>>>(
        bias, out);
}

// round 3
// speedup vs baseline: 1.1508x; 1.1508x over previous
#include <cuda_runtime.h>
#include <cuda_fp16.h>
#include <cstdint>
#include <cstddef>

// ============================================================================
// SparseLinear: y[8192,4096] = x[8192,4096] @ W[4096,4096] + bias[4096]
// fp16 mma.sync GEMM (tcgen05 blocked: harness compiles PTX at compute_103).
// R2: BM=128 BN=256, warp tile 64x64 (ldsm:mma 0.25), merged prep kernel,
//     recomputed cp.async addressing to hold register count ~180.
// ============================================================================

#define D_DIM 4096
#define M_DIM 8192
#define BM 128
#define BN 256
#define BK 64
#define STAGES 4
#define KTILES (D_DIM / BK)            // 64
#define THREADS 256
#define A_TILE_BYTES (BM * BK * 2)     // 16384
#define B_TILE_BYTES (BN * BK * 2)     // 32768
#define STAGE_BYTES (A_TILE_BYTES + B_TILE_BYTES)   // 49152
#define SMEM_SIZE (STAGES * STAGE_BYTES)            // 196608
#define GRANULES (STAGE_BYTES / 16)    // 3072 -> 12 per thread

__device__ __align__(256) __half g_XH[(size_t)M_DIM * D_DIM];
__device__ __align__(256) __half g_WTH[(size_t)D_DIM * D_DIM];

// ---------------------------------------------------------------------------
// helpers
// ---------------------------------------------------------------------------
__device__ __forceinline__ uint32_t smem_u32(const void* p) {
    uint32_t a;
    asm("{ .reg .u64 t; cvta.to.shared.u64 t, %1; cvt.u32.u64 %0, t; }"
        : "=r"(a) : "l"(p));
    return a;
}

__device__ __forceinline__ void cp_async16(uint32_t dst, const void* src) {
    asm volatile("cp.async.cg.shared.global [%0], [%1], 16;"
                 :: "r"(dst), "l"(src));
}
__device__ __forceinline__ void cp_commit() {
    asm volatile("cp.async.commit_group;" ::: "memory");
}

__device__ __forceinline__ void ldsm_x4(uint32_t* r, uint32_t addr) {
    asm volatile("ldmatrix.sync.aligned.m8n8.x4.shared.b16 {%0,%1,%2,%3}, [%4];"
                 : "=r"(r[0]), "=r"(r[1]), "=r"(r[2]), "=r"(r[3])
                 : "r"(addr));
}

__device__ __forceinline__ void mma16816(float* c, const uint32_t* a,
                                         uint32_t b0, uint32_t b1) {
    asm volatile(
        "mma.sync.aligned.m16n8k16.row.col.f32.f16.f16.f32 "
        "{%0,%1,%2,%3}, {%4,%5,%6,%7}, {%8,%9}, {%0,%1,%2,%3};"
        : "+f"(c[0]), "+f"(c[1]), "+f"(c[2]), "+f"(c[3])
        : "r"(a[0]), "r"(a[1]), "r"(a[2]), "r"(a[3]), "r"(b0), "r"(b1));
}

// ---------------------------------------------------------------------------
// Merged prep: blocks [0, XBLK) convert x -> fp16; rest transpose+convert W.
// ---------------------------------------------------------------------------
#define XBLK ((int)((size_t)M_DIM * D_DIM / 4 / 256))   // 32768

__global__ void prep_kernel(const float4* __restrict__ x,
                            const float* __restrict__ W) {
    if (blockIdx.x < XBLK) {
        size_t i = (size_t)blockIdx.x * 256 + threadIdx.x;
        float4 v = x[i];
        __half2 h0 = __floats2half2_rn(v.x, v.y);
        __half2 h1 = __floats2half2_rn(v.z, v.w);
        uint2 o;
        o.x = *reinterpret_cast<uint32_t*>(&h0);
        o.y = *reinterpret_cast<uint32_t*>(&h1);
        reinterpret_cast<uint2*>(g_XH)[i] = o;
    } else {
        __shared__ float t[32][33];
        int b = blockIdx.x - XBLK;            // 128 x 128 tile grid
        int bx = (b & 127) * 32, by = (b >> 7) * 32;  // bx: n, by: k
        int tx = threadIdx.x & 31, ty = threadIdx.x >> 5;
#pragma unroll
        for (int i = 0; i < 32; i += 8)
            t[ty + i][tx] = W[(size_t)(by + ty + i) * D_DIM + bx + tx];
        __syncthreads();
#pragma unroll
        for (int i = 0; i < 32; i += 8)
            g_WTH[(size_t)(bx + ty + i) * D_DIM + by + tx] =
                __float2half_rn(t[tx][ty + i]);
    }
}

// ---------------------------------------------------------------------------
// GEMM. grid (N/BN, M/BM) = (16, 64), 256 threads = 8 warps (2m x 4n),
// warp tile 64x64. SMEM stage: [A 128x64 | B 256x64] halves, 128B rows,
// granule-XOR swizzle.
// ---------------------------------------------------------------------------
__global__ __launch_bounds__(THREADS, 1)
void gemm_f16_kernel(const float* __restrict__ bias, float* __restrict__ out) {
    extern __shared__ char smem[];
    const uint32_t sbase = smem_u32(smem);
    const int tid = threadIdx.x;
    const int wid = tid >> 5;
    const int l = tid & 31;
    const int bm = blockIdx.y * BM;
    const int bn = blockIdx.x * BN;
    const int wm = (wid >> 2) * 64;   // 2 warps in m
    const int wn = (wid & 3) * 64;    // 4 warps in n

    const __half* abase = g_XH + (size_t)bm * D_DIM;
    const __half* bbase = g_WTH + (size_t)bn * D_DIM;

    // 12 granules per thread per stage; addresses recomputed (register diet)
    auto load_tile = [&](int kt, int slot) {
        const uint32_t sb = sbase + (uint32_t)slot * STAGE_BYTES;
        const __half* kofs_a = abase + (size_t)kt * BK;
        const __half* kofs_b = bbase + (size_t)kt * BK;
#pragma unroll
        for (int j = 0; j < 12; j++) {
            int gi = tid + j * 256;
            int isB = (gi >= 1024);
            int idx = isB ? gi - 1024 : gi;
            int r = idx >> 3;
            int g = idx & 7;
            const __half* src =
                (isB ? kofs_b + (size_t)r * D_DIM : kofs_a + (size_t)r * D_DIM)
                + g * 8;
            uint32_t dst = sb + (uint32_t)(isB ? A_TILE_BYTES : 0) +
                           (uint32_t)(r * 128) +
                           (uint32_t)((g ^ (r & 7)) << 4);
            cp_async16(dst, src);
        }
    };

#pragma unroll
    for (int s = 0; s < STAGES - 1; s++) { load_tile(s, s); cp_commit(); }

    float acc[4][8][4] = {};

    // ldmatrix lane addressing
    const int arow_l = (l & 15);
    const int akg0 = (l >> 4);
    const int brow_off = (l & 7) + ((l >> 4) << 3);
    const int bkg0 = (l >> 3) & 1;

    for (int kt = 0; kt < KTILES; kt++) {
        asm volatile("cp.async.wait_group %0;" :: "n"(STAGES - 2) : "memory");
        __syncthreads();
        const int pf = kt + STAGES - 1;
        if (pf < KTILES) load_tile(pf, pf & (STAGES - 1));
        cp_commit();

        const uint32_t stg = sbase + (uint32_t)(kt & (STAGES - 1)) * STAGE_BYTES;
#pragma unroll
        for (int ks = 0; ks < 4; ks++) {
            uint32_t a[4][4];
#pragma unroll
            for (int mt = 0; mt < 4; mt++) {
                int row = wm + mt * 16 + arow_l;
                uint32_t addr = stg + (uint32_t)(row * 128) +
                                (uint32_t)(((2 * ks + akg0) ^ (row & 7)) << 4);
                ldsm_x4(a[mt], addr);
            }
            uint32_t b[4][4];
#pragma unroll
            for (int p = 0; p < 4; p++) {
                int row = wn + p * 16 + brow_off;
                uint32_t addr = stg + A_TILE_BYTES + (uint32_t)(row * 128) +
                                (uint32_t)(((2 * ks + bkg0) ^ (row & 7)) << 4);
                ldsm_x4(b[p], addr);
            }
#pragma unroll
            for (int mt = 0; mt < 4; mt++)
#pragma unroll
                for (int p = 0; p < 4; p++) {
                    mma16816(acc[mt][2 * p],     a[mt], b[p][0], b[p][1]);
                    mma16816(acc[mt][2 * p + 1], a[mt], b[p][2], b[p][3]);
                }
        }
    }

    // --- epilogue: y = acc + bias
    const int grp = l >> 2, tig = l & 3;
#pragma unroll
    for (int mt = 0; mt < 4; mt++) {
        const size_t row0 = (size_t)(bm + wm + mt * 16 + grp);
#pragma unroll
        for (int nt = 0; nt < 8; nt++) {
            const int col = bn + wn + nt * 8 + tig * 2;
            const float2 bv = *reinterpret_cast<const float2*>(bias + col);
            float2 v0, v1;
            v0.x = acc[mt][nt][0] + bv.x;
            v0.y = acc[mt][nt][1] + bv.y;
            v1.x = acc[mt][nt][2] + bv.x;
            v1.y = acc[mt][nt][3] + bv.y;
            *reinterpret_cast<float2*>(out + row0 * D_DIM + col) = v0;
            *reinterpret_cast<float2*>(out + (row0 + 8) * D_DIM + col) = v1;
        }
    }
}

// ---------------------------------------------------------------------------
// Launch
// ---------------------------------------------------------------------------
extern "C" void kernel_launch(void* const* d_in, const int* in_sizes, int n_in,
                              void* d_out, int out_size) {
    const float* x    = (const float*)d_in[0];
    const float* W    = (const float*)d_in[1];
    const float* bias = (const float*)d_in[2];
    float* out = (float*)d_out;

    cudaFuncSetAttribute(gemm_f16_kernel,
                         cudaFuncAttributeMaxDynamicSharedMemorySize, SMEM_SIZE);

    prep_kernel<<<XBLK + 128 * 128, 256>>>((const float4*)x, W);
    gemm_f16_kernel<<<dim3(D_DIM / BN, M_DIM / BM), THREADS, SMEM_SIZE>>>(
        bias, out);
}

// round 4
// speedup vs baseline: 1.4022x; 1.2185x over previous
#include <cuda_runtime.h>
#include <cuda_fp16.h>
#include <cstdint>
#include <cstddef>

// ============================================================================
// SparseLinear: y[8192,4096] = x[8192,4096] @ W[4096,4096] + bias[4096]
// fp16 mma.sync GEMM (tcgen05 blocked: harness compiles PTX at compute_103).
// R3: fragment double-buffering (ldsm ks+1 overlapped with mma ks), lean
//     cp.async addressing (structured strides), BM=128 BN=256 BK=64, 4 stages.
// ============================================================================

#define D_DIM 4096
#define M_DIM 8192
#define BM 128
#define BN 256
#define BK 64
#define STAGES 4
#define KTILES (D_DIM / BK)            // 64
#define THREADS 256
#define A_TILE_BYTES (BM * BK * 2)     // 16384
#define B_TILE_BYTES (BN * BK * 2)     // 32768
#define STAGE_BYTES (A_TILE_BYTES + B_TILE_BYTES)   // 49152
#define SMEM_SIZE (STAGES * STAGE_BYTES)            // 196608

__device__ __align__(256) __half g_XH[(size_t)M_DIM * D_DIM];
__device__ __align__(256) __half g_WTH[(size_t)D_DIM * D_DIM];

// ---------------------------------------------------------------------------
// helpers
// ---------------------------------------------------------------------------
__device__ __forceinline__ uint32_t smem_u32(const void* p) {
    uint32_t a;
    asm("{ .reg .u64 t; cvta.to.shared.u64 t, %1; cvt.u32.u64 %0, t; }"
        : "=r"(a) : "l"(p));
    return a;
}

__device__ __forceinline__ void cp_async16(uint32_t dst, const void* src) {
    asm volatile("cp.async.cg.shared.global [%0], [%1], 16;"
                 :: "r"(dst), "l"(src));
}
__device__ __forceinline__ void cp_commit() {
    asm volatile("cp.async.commit_group;" ::: "memory");
}

__device__ __forceinline__ void ldsm_x4(uint32_t* r, uint32_t addr) {
    asm volatile("ldmatrix.sync.aligned.m8n8.x4.shared.b16 {%0,%1,%2,%3}, [%4];"
                 : "=r"(r[0]), "=r"(r[1]), "=r"(r[2]), "=r"(r[3])
                 : "r"(addr));
}

__device__ __forceinline__ void mma16816(float* c, const uint32_t* a,
                                         uint32_t b0, uint32_t b1) {
    asm volatile(
        "mma.sync.aligned.m16n8k16.row.col.f32.f16.f16.f32 "
        "{%0,%1,%2,%3}, {%4,%5,%6,%7}, {%8,%9}, {%0,%1,%2,%3};"
        : "+f"(c[0]), "+f"(c[1]), "+f"(c[2]), "+f"(c[3])
        : "r"(a[0]), "r"(a[1]), "r"(a[2]), "r"(a[3]), "r"(b0), "r"(b1));
}

// ---------------------------------------------------------------------------
// Merged prep: blocks [0, XBLK) convert x -> fp16; rest transpose+convert W.
// ---------------------------------------------------------------------------
#define XBLK ((int)((size_t)M_DIM * D_DIM / 4 / 256))   // 32768

__global__ void prep_kernel(const float4* __restrict__ x,
                            const float* __restrict__ W) {
    if (blockIdx.x < XBLK) {
        size_t i = (size_t)blockIdx.x * 256 + threadIdx.x;
        float4 v = x[i];
        __half2 h0 = __floats2half2_rn(v.x, v.y);
        __half2 h1 = __floats2half2_rn(v.z, v.w);
        uint2 o;
        o.x = *reinterpret_cast<uint32_t*>(&h0);
        o.y = *reinterpret_cast<uint32_t*>(&h1);
        reinterpret_cast<uint2*>(g_XH)[i] = o;
    } else {
        __shared__ float t[32][33];
        int b = blockIdx.x - XBLK;                     // 128 x 128 tile grid
        int bx = (b & 127) * 32, by = (b >> 7) * 32;   // bx: n, by: k
        int tx = threadIdx.x & 31, ty = threadIdx.x >> 5;
#pragma unroll
        for (int i = 0; i < 32; i += 8)
            t[ty + i][tx] = W[(size_t)(by + ty + i) * D_DIM + bx + tx];
        __syncthreads();
#pragma unroll
        for (int i = 0; i < 32; i += 8)
            g_WTH[(size_t)(bx + ty + i) * D_DIM + by + tx] =
                __float2half_rn(t[tx][ty + i]);
    }
}

// ---------------------------------------------------------------------------
// GEMM. grid (16, 64), 256 threads = 8 warps (2m x 4n), warp tile 64x64.
// SMEM stage: [A 128x64 | B 256x64] halves, 128B rows, granule-XOR swizzle.
// ---------------------------------------------------------------------------
__global__ __launch_bounds__(THREADS, 1)
void gemm_f16_kernel(const float* __restrict__ bias, float* __restrict__ out) {
    extern __shared__ char smem[];
    const uint32_t sbase = smem_u32(smem);
    const int tid = threadIdx.x;
    const int wid = tid >> 5;
    const int l = tid & 31;
    const int bm = blockIdx.y * BM;
    const int bn = blockIdx.x * BN;
    const int wm = (wid >> 2) * 64;   // 2 warps in m
    const int wn = (wid & 3) * 64;    // 4 warps in n

    // --- lean cp.async addressing: granule j covers row (tid>>3)+j*32 ---
    const char* a_src = (const char*)(g_XH +
        (size_t)(bm + (tid >> 3)) * D_DIM + (tid & 7) * 8);
    const char* b_src = (const char*)(g_WTH +
        (size_t)(bn + (tid >> 3)) * D_DIM + (tid & 7) * 8);
    const uint32_t sdst_a0 = (uint32_t)((tid >> 3) * 128) +
                             ((uint32_t)((tid & 7) ^ ((tid >> 3) & 7)) << 4);
    const uint32_t sdst_b0 = sdst_a0;   // same row/granule pattern

    auto load_tile = [&](int kt, int slot) {
        const uint32_t sb = sbase + (uint32_t)slot * STAGE_BYTES;
        const char* ak = a_src + (size_t)kt * (BK * 2);
        const char* bk = b_src + (size_t)kt * (BK * 2);
#pragma unroll
        for (int j = 0; j < 4; j++)
            cp_async16(sb + sdst_a0 + j * 4096,
                       ak + (size_t)j * 32 * D_DIM * 2);
#pragma unroll
        for (int j = 0; j < 8; j++)
            cp_async16(sb + A_TILE_BYTES + sdst_b0 + j * 4096,
                       bk + (size_t)j * 32 * D_DIM * 2);
    };

    // --- ldmatrix addressing ---
    const int arow_l = (l & 15);
    const int akg0 = (l >> 4);
    const int brow_off = (l & 7) + ((l >> 4) << 3);
    const int bkg0 = (l >> 3) & 1;
    const uint32_t a_base = (uint32_t)((wm + arow_l) * 128);
    const uint32_t b_base = (uint32_t)((wn + brow_off) * 128) + A_TILE_BYTES;
    const uint32_t kxor = (uint32_t)(l & 7);   // row&7 for both A and B frags

    auto load_frags = [&](uint32_t stg, int ks,
                          uint32_t (&A)[4][4], uint32_t (&B)[4][4]) {
#pragma unroll
        for (int mt = 0; mt < 4; mt++)
            ldsm_x4(A[mt], stg + a_base + mt * 2048 +
                           ((((uint32_t)(2 * ks) + akg0) ^ kxor) << 4));
#pragma unroll
        for (int p = 0; p < 4; p++)
            ldsm_x4(B[p], stg + b_base + p * 2048 +
                          ((((uint32_t)(2 * ks) + bkg0) ^ kxor) << 4));
    };

    float acc[4][8][4] = {};
    uint32_t Abuf[2][4][4], Bbuf[2][4][4];

    auto mma_all = [&](uint32_t (&A)[4][4], uint32_t (&B)[4][4]) {
#pragma unroll
        for (int mt = 0; mt < 4; mt++)
#pragma unroll
            for (int p = 0; p < 4; p++) {
                mma16816(acc[mt][2 * p],     A[mt], B[p][0], B[p][1]);
                mma16816(acc[mt][2 * p + 1], A[mt], B[p][2], B[p][3]);
            }
    };

    // --- prologue: fill 3 stages, arm first fragment buffer ---
#pragma unroll
    for (int s = 0; s < STAGES - 1; s++) { load_tile(s, s); cp_commit(); }
    asm volatile("cp.async.wait_group %0;" :: "n"(STAGES - 2) : "memory");
    __syncthreads();
    load_frags(sbase, 0, Abuf[0], Bbuf[0]);

    for (int kt = 0; kt < KTILES; kt++) {
        const uint32_t stg = sbase + (uint32_t)(kt & 3) * STAGE_BYTES;
        const int pf = kt + STAGES - 1;
        if (pf < KTILES) load_tile(pf, pf & 3);
        cp_commit();

#pragma unroll
        for (int ks = 0; ks < 4; ks++) {
            if (ks < 3)
                load_frags(stg, ks + 1, Abuf[(ks + 1) & 1], Bbuf[(ks + 1) & 1]);
            mma_all(Abuf[ks & 1], Bbuf[ks & 1]);
        }

        asm volatile("cp.async.wait_group %0;" :: "n"(STAGES - 2) : "memory");
        __syncthreads();
        if (kt + 1 < KTILES)
            load_frags(sbase + (uint32_t)((kt + 1) & 3) * STAGE_BYTES, 0,
                       Abuf[0], Bbuf[0]);
    }

    // --- epilogue: y = acc + bias ---
    const int grp = l >> 2, tig = l & 3;
#pragma unroll
    for (int mt = 0; mt < 4; mt++) {
        const size_t row0 = (size_t)(bm + wm + mt * 16 + grp);
#pragma unroll
        for (int nt = 0; nt < 8; nt++) {
            const int col = bn + wn + nt * 8 + tig * 2;
            const float2 bv = *reinterpret_cast<const float2*>(bias + col);
            float2 v0, v1;
            v0.x = acc[mt][nt][0] + bv.x;
            v0.y = acc[mt][nt][1] + bv.y;
            v1.x = acc[mt][nt][2] + bv.x;
            v1.y = acc[mt][nt][3] + bv.y;
            *reinterpret_cast<float2*>(out + row0 * D_DIM + col) = v0;
            *reinterpret_cast<float2*>(out + (row0 + 8) * D_DIM + col) = v1;
        }
    }
}

// ---------------------------------------------------------------------------
// Launch
// ---------------------------------------------------------------------------
extern "C" void kernel_launch(void* const* d_in, const int* in_sizes, int n_in,
                              void* d_out, int out_size) {
    const float* x    = (const float*)d_in[0];
    const float* W    = (const float*)d_in[1];
    const float* bias = (const float*)d_in[2];
    float* out = (float*)d_out;

    cudaFuncSetAttribute(gemm_f16_kernel,
                         cudaFuncAttributeMaxDynamicSharedMemorySize, SMEM_SIZE);

    prep_kernel<<<XBLK + 128 * 128, 256>>>((const float4*)x, W);
    gemm_f16_kernel<<<dim3(D_DIM / BN, M_DIM / BM), THREADS, SMEM_SIZE>>>(
        bias, out);
}